// round 10
// baseline (speedup 1.0000x reference)
#include <cuda_runtime.h>
#include <cuda_fp16.h>
#include <cstdint>

// Problem constants (fixed by the reference)
#define Bn   4
#define Cn   128
#define HWn  16384      // 128*128
#define Pn   4096
#define Vn   32
#define PT   8          // points per block (1 warp per point)
#define BLK_PER_BATCH 512

// Scratch for transposed x in fp16: [B][HW][C] half = 16.8 MB.
__device__ __align__(16) __half g_xt[(size_t)Bn * HWn * Cn];
// Per-batch transpose-completion counters (reset by a tiny kernel each launch).
__device__ int g_done[Bn];

// ---------------------------------------------------------------------------
// Kernel 0: reset the per-batch counters (graph replays must start clean).
// ---------------------------------------------------------------------------
__global__ void reset_kernel()
{
    if (threadIdx.x < Bn) g_done[threadIdx.x] = 0;
}

// ---------------------------------------------------------------------------
// Fused kernel: each block transposes 2 tiles of its batch, publishes, spins
// until its whole batch is transposed, then gathers 8 points of that batch.
// Transpose (DRAM-bound) overlaps gather (L2-slice-bound) across blocks.
// ---------------------------------------------------------------------------
__global__ __launch_bounds__(256, 8) void fused_kernel(
    const float* __restrict__ x,             // [B, C, HW]
    const int*   __restrict__ vote_index,    // [32768, 32]
    const float* __restrict__ vote_weight,   // [32768, 32]
    const int*   __restrict__ inds,          // [B, P] int32
    float*       __restrict__ out)           // [B, C, P]
{
    __shared__ union {
        float tile[64][33];      // transpose staging (8448 B)
        float s_out[PT][132];    // gather output staging (4224 B)
    } u;
    __shared__ uint2 s_iw[PT][Vn];   // {hw * (Cn/4) offset, half2(w,w) bits}

    const int bid  = blockIdx.x;
    const int b    = bid >> 9;            // batch (blocks are batch-major)
    const int j    = bid & (BLK_PER_BATCH - 1);
    const int t    = threadIdx.x;
    const int tx   = t & 31;
    const int ty   = t >> 5;              // 0..7
    const int warp = ty;
    const int lane = tx;

    // ---- Phase 1: transpose 2 tiles (64c x 32hw each) of batch b ----------
    __half2* xt2 = reinterpret_cast<__half2*>(g_xt);
    #pragma unroll
    for (int tt = 0; tt < 2; tt++) {
        const int tile_id = 2 * j + tt;        // 0..1023 within batch
        const int c0  = (tile_id & 1) * 64;
        const int hw0 = (tile_id >> 1) * 32;

        #pragma unroll
        for (int jj = 0; jj < 8; jj++) {
            const int cl = ty + jj * 8;
            u.tile[cl][tx] = x[((size_t)b * Cn + c0 + cl) * HWn + hw0 + tx];
        }
        __syncthreads();

        #pragma unroll
        for (int jj = 0; jj < 4; jj++) {
            const int idx  = jj * 256 + t;
            const int hw_l = idx >> 5;
            const int c2   = idx & 31;
            const float f0 = u.tile[c2 * 2][hw_l];
            const float f1 = u.tile[c2 * 2 + 1][hw_l];
            xt2[(((size_t)b * HWn + hw0 + hw_l) * Cn + c0) / 2 + c2] =
                __floats2half2_rn(f0, f1);
        }
        __syncthreads();
    }
    __threadfence();
    if (t == 0) atomicAdd(&g_done[b], 1);

    // ---- Stage vote indices + weights (independent of xt; overlaps wait) --
    const int p0 = j * PT;
    {
        const int sph = inds[(size_t)b * Pn + p0 + warp];   // warp-uniform
        const int hw  = vote_index[(size_t)sph * Vn + lane];
        const float w = vote_weight[(size_t)sph * Vn + lane];
        const __half2 w2 = __float2half2_rn(w);
        s_iw[warp][lane] = make_uint2((unsigned)hw * (Cn / 4),
                                      *reinterpret_cast<const unsigned*>(&w2));
    }

    // ---- Wait until batch b is fully transposed ---------------------------
    if (t == 0) {
        while (*((volatile int*)&g_done[b]) < BLK_PER_BATCH) __nanosleep(64);
    }
    __syncthreads();
    __threadfence();

    // ---- Phase 2: gather + vote accumulate (r5 body, proven fastest) ------
    const uint2* xt = reinterpret_cast<const uint2*>(g_xt) + (size_t)b * HWn * (Cn / 4);

    float2 accA = make_float2(0.f, 0.f);
    float2 accB = make_float2(0.f, 0.f);

    #pragma unroll
    for (int g = 0; g < Vn / 4; g++) {           // 8 groups of 4 votes
        const uint2 iw0 = s_iw[warp][g * 4 + 0];
        const uint2 iw1 = s_iw[warp][g * 4 + 1];
        const uint2 iw2 = s_iw[warp][g * 4 + 2];
        const uint2 iw3 = s_iw[warp][g * 4 + 3];
        const uint2 r0 = __ldg(&xt[iw0.x + lane]);
        const uint2 r1 = __ldg(&xt[iw1.x + lane]);
        const uint2 r2 = __ldg(&xt[iw2.x + lane]);
        const uint2 r3 = __ldg(&xt[iw3.x + lane]);

        __half2 h0 = __float2half2_rn(0.f);
        __half2 h1 = __float2half2_rn(0.f);
        h0 = __hfma2(*reinterpret_cast<const __half2*>(&r0.x),
                     *reinterpret_cast<const __half2*>(&iw0.y), h0);
        h1 = __hfma2(*reinterpret_cast<const __half2*>(&r0.y),
                     *reinterpret_cast<const __half2*>(&iw0.y), h1);
        h0 = __hfma2(*reinterpret_cast<const __half2*>(&r1.x),
                     *reinterpret_cast<const __half2*>(&iw1.y), h0);
        h1 = __hfma2(*reinterpret_cast<const __half2*>(&r1.y),
                     *reinterpret_cast<const __half2*>(&iw1.y), h1);
        h0 = __hfma2(*reinterpret_cast<const __half2*>(&r2.x),
                     *reinterpret_cast<const __half2*>(&iw2.y), h0);
        h1 = __hfma2(*reinterpret_cast<const __half2*>(&r2.y),
                     *reinterpret_cast<const __half2*>(&iw2.y), h1);
        h0 = __hfma2(*reinterpret_cast<const __half2*>(&r3.x),
                     *reinterpret_cast<const __half2*>(&iw3.y), h0);
        h1 = __hfma2(*reinterpret_cast<const __half2*>(&r3.y),
                     *reinterpret_cast<const __half2*>(&iw3.y), h1);

        const float2 f0 = __half22float2(h0);
        const float2 f1 = __half22float2(h1);
        accA.x += f0.x; accA.y += f0.y;
        accB.x += f1.x; accB.y += f1.y;
    }

    *reinterpret_cast<float4*>(&u.s_out[warp][lane * 4]) =
        make_float4(accA.x, accA.y, accB.x, accB.y);
    __syncthreads();

    // Write out [C][PT] tile: 8 consecutive p per c row.
    #pragma unroll
    for (int i = t; i < Cn * PT; i += 256) {
        const int c  = i >> 3;   // i / PT
        const int pl = i & 7;    // i % PT
        out[((size_t)b * Cn + c) * Pn + p0 + pl] = u.s_out[pl][c];
    }
}

// ---------------------------------------------------------------------------
// Launch
// ---------------------------------------------------------------------------
extern "C" void kernel_launch(void* const* d_in, const int* in_sizes, int n_in,
                              void* d_out, int out_size)
{
    const float* x           = (const float*)d_in[0];   // [4,128,128,128]
    const int*   vote_index  = (const int*)d_in[1];     // [32768,32]
    const float* vote_weight = (const float*)d_in[2];   // [32768,32]
    const int*   inds        = (const int*)d_in[3];     // [4,4096] int32
    float*       out         = (float*)d_out;           // [4,128,4096]

    reset_kernel<<<1, 32>>>();
    fused_kernel<<<Bn * BLK_PER_BATCH, 256>>>(x, vote_index, vote_weight, inds, out);
}

// round 11
// speedup vs baseline: 1.2531x; 1.2531x over previous
#include <cuda_runtime.h>
#include <cuda_fp16.h>
#include <cstdint>

// Problem constants (fixed by the reference)
#define Bn   4
#define Cn   128
#define HWn  16384      // 128*128
#define Pn   4096
#define Vn   32
#define PT   8          // points per block (1 warp per point)

// Split-plane fp16 scratch: plane A = channels 0..63, plane B = channels
// 64..127, each [B][HW][64] halves (128B rows). The two planes are 8MB apart,
// so the two 128B lines of one vote map to DIFFERENT LTS slices (the lines of
// a contiguous 256B row differ only in bit 7, which is transparent in the
// addr->LTS hash -> they would serialize in one slice).
#define PLANE_HALF2 ((size_t)Bn * HWn * 32)   // half2 units per plane
#define PLANE_UINT2 ((size_t)Bn * HWn * 16)   // uint2 units per plane
__device__ __align__(16) __half g_xt[(size_t)2 * Bn * HWn * 64];

// ---------------------------------------------------------------------------
// Kernel 1: transpose + downconvert x [B,C,HW] fp32 -> split planes.
// ---------------------------------------------------------------------------
__global__ __launch_bounds__(256) void transpose_fp16_kernel(const float* __restrict__ x)
{
    __shared__ float tile[64][33];

    const int b   = blockIdx.z;
    const int hw0 = blockIdx.x * 32;
    const int c0  = blockIdx.y * 64;     // 0 or 64 -> plane select
    const int tx  = threadIdx.x;   // 0..31
    const int ty  = threadIdx.y;   // 0..7

    #pragma unroll
    for (int j = 0; j < 8; j++) {
        const int cl = ty + j * 8;
        tile[cl][tx] = x[((size_t)b * Cn + c0 + cl) * HWn + hw0 + tx];
    }
    __syncthreads();

    const int t = ty * 32 + tx;
    __half2* xt2 = reinterpret_cast<__half2*>(g_xt) + (c0 >= 64 ? PLANE_HALF2 : 0);
    #pragma unroll
    for (int j = 0; j < 4; j++) {
        const int idx  = j * 256 + t;          // 0..1023
        const int hw_l = idx >> 5;             // 0..31
        const int c2   = idx & 31;             // half2 index within 64-ch row
        const float f0 = tile[c2 * 2][hw_l];
        const float f1 = tile[c2 * 2 + 1][hw_l];
        xt2[((size_t)b * HWn + hw0 + hw_l) * 32 + c2] = __floats2half2_rn(f0, f1);
    }
}

// ---------------------------------------------------------------------------
// Kernel 2: gather + vote accumulate. ONE WARP PER POINT.
// Lanes 0-15 read plane A (channels 4l..4l+3), lanes 16-31 plane B (channels
// 4l..4l+3 with l>=16 -> 64+...). One LDG.64 per lane per vote; the warp's
// 256B now spans two LTS slices instead of serializing in one.
// ---------------------------------------------------------------------------
__global__ __launch_bounds__(256, 8) void gather_kernel(
    const int*   __restrict__ vote_index,   // [32768, 32]
    const float* __restrict__ vote_weight,  // [32768, 32]
    const int*   __restrict__ inds,         // [B, P] int32
    float*       __restrict__ out)          // [B, C, P]
{
    __shared__ uint2 s_iw[PT][Vn];   // {hw * 16 (uint2 row offset), half2(w,w)}
    __shared__ float s_out[PT][132];

    const int b    = blockIdx.y;
    const int p0   = blockIdx.x * PT;
    const int t    = threadIdx.x;
    const int warp = t >> 5;
    const int lane = t & 31;

    // Stage fused (row offset in uint2 units, weight half2) per vote.
    {
        const int sph = inds[(size_t)b * Pn + p0 + warp];   // warp-uniform
        const int hw  = vote_index[(size_t)sph * Vn + lane];
        const float w = vote_weight[(size_t)sph * Vn + lane];
        const __half2 w2 = __float2half2_rn(w);
        s_iw[warp][lane] = make_uint2((unsigned)hw * 16u,
                                      *reinterpret_cast<const unsigned*>(&w2));
    }
    __syncthreads();

    // Per-lane base: plane select + batch base + lane slot within 16-uint2 row.
    const uint2* xt = reinterpret_cast<const uint2*>(g_xt)
                    + (lane >= 16 ? PLANE_UINT2 : 0)
                    + (size_t)b * HWn * 16
                    + (lane & 15);

    float2 accA = make_float2(0.f, 0.f);
    float2 accB = make_float2(0.f, 0.f);

    #pragma unroll
    for (int g = 0; g < Vn / 4; g++) {           // 8 groups of 4 votes
        const uint2 iw0 = s_iw[warp][g * 4 + 0];
        const uint2 iw1 = s_iw[warp][g * 4 + 1];
        const uint2 iw2 = s_iw[warp][g * 4 + 2];
        const uint2 iw3 = s_iw[warp][g * 4 + 3];
        const uint2 r0 = __ldg(xt + iw0.x);
        const uint2 r1 = __ldg(xt + iw1.x);
        const uint2 r2 = __ldg(xt + iw2.x);
        const uint2 r3 = __ldg(xt + iw3.x);

        __half2 h0 = __float2half2_rn(0.f);
        __half2 h1 = __float2half2_rn(0.f);
        h0 = __hfma2(*reinterpret_cast<const __half2*>(&r0.x),
                     *reinterpret_cast<const __half2*>(&iw0.y), h0);
        h1 = __hfma2(*reinterpret_cast<const __half2*>(&r0.y),
                     *reinterpret_cast<const __half2*>(&iw0.y), h1);
        h0 = __hfma2(*reinterpret_cast<const __half2*>(&r1.x),
                     *reinterpret_cast<const __half2*>(&iw1.y), h0);
        h1 = __hfma2(*reinterpret_cast<const __half2*>(&r1.y),
                     *reinterpret_cast<const __half2*>(&iw1.y), h1);
        h0 = __hfma2(*reinterpret_cast<const __half2*>(&r2.x),
                     *reinterpret_cast<const __half2*>(&iw2.y), h0);
        h1 = __hfma2(*reinterpret_cast<const __half2*>(&r2.y),
                     *reinterpret_cast<const __half2*>(&iw2.y), h1);
        h0 = __hfma2(*reinterpret_cast<const __half2*>(&r3.x),
                     *reinterpret_cast<const __half2*>(&iw3.y), h0);
        h1 = __hfma2(*reinterpret_cast<const __half2*>(&r3.y),
                     *reinterpret_cast<const __half2*>(&iw3.y), h1);

        const float2 f0 = __half22float2(h0);
        const float2 f1 = __half22float2(h1);
        accA.x += f0.x; accA.y += f0.y;
        accB.x += f1.x; accB.y += f1.y;
    }

    // Lane l holds channels 4l..4l+3 (plane split preserves this mapping).
    *reinterpret_cast<float4*>(&s_out[warp][lane * 4]) =
        make_float4(accA.x, accA.y, accB.x, accB.y);
    __syncthreads();

    // Write out [C][PT] tile: 8 consecutive p per c row.
    #pragma unroll
    for (int i = t; i < Cn * PT; i += 256) {
        const int c  = i >> 3;   // i / PT
        const int pl = i & 7;    // i % PT
        out[((size_t)b * Cn + c) * Pn + p0 + pl] = s_out[pl][c];
    }
}

// ---------------------------------------------------------------------------
// Launch
// ---------------------------------------------------------------------------
extern "C" void kernel_launch(void* const* d_in, const int* in_sizes, int n_in,
                              void* d_out, int out_size)
{
    const float* x           = (const float*)d_in[0];   // [4,128,128,128]
    const int*   vote_index  = (const int*)d_in[1];     // [32768,32]
    const float* vote_weight = (const float*)d_in[2];   // [32768,32]
    const int*   inds        = (const int*)d_in[3];     // [4,4096] int32
    float*       out         = (float*)d_out;           // [4,128,4096]

    {
        dim3 grid(HWn / 32, Cn / 64, Bn);   // (512, 2, 4)
        dim3 block(32, 8);
        transpose_fp16_kernel<<<grid, block>>>(x);
    }
    {
        dim3 grid(Pn / PT, Bn);             // (512, 4) = 2048 blocks
        gather_kernel<<<grid, 256>>>(vote_index, vote_weight, inds, out);
    }
}

// round 12
// speedup vs baseline: 1.2670x; 1.0111x over previous
#include <cuda_runtime.h>
#include <cuda_fp16.h>
#include <cstdint>

// Problem constants (fixed by the reference)
#define Bn   4
#define Cn   128
#define HWn  16384      // 128*128
#define Pn   4096
#define Vn   32
#define PT   8          // points per block (1 warp per point)

// Split-plane fp16 scratch: plane A = channels 0..63, plane B = channels
// 64..127, each [B][HW][64] halves (128B rows).
#define PLANE_HALF2 ((size_t)Bn * HWn * 32)   // half2 units per plane
#define PLANE_UINT2 ((size_t)Bn * HWn * 16)   // uint2 units per plane
__device__ __align__(16) __half g_xt[(size_t)2 * Bn * HWn * 64];

// Gather load: read-only, DO NOT allocate an L1 line. The gather working set
// (16.8MB) never hits in L1 (228KB), so every normal LDG allocates+fills a
// 128B line that is evicted unused -- hypothesized hidden binder (~10 cyc/vote
// of L1 fill wavefronts). no_allocate delivers sectors straight to registers.
__device__ __forceinline__ uint2 ldg_na(const uint2* p)
{
    uint2 r;
    asm volatile("ld.global.nc.L1::no_allocate.v2.u32 {%0,%1}, [%2];"
                 : "=r"(r.x), "=r"(r.y) : "l"(p));
    return r;
}

// ---------------------------------------------------------------------------
// Kernel 1: transpose + downconvert x [B,C,HW] fp32 -> split planes.
// ---------------------------------------------------------------------------
__global__ __launch_bounds__(256) void transpose_fp16_kernel(const float* __restrict__ x)
{
    __shared__ float tile[64][33];

    const int b   = blockIdx.z;
    const int hw0 = blockIdx.x * 32;
    const int c0  = blockIdx.y * 64;     // 0 or 64 -> plane select
    const int tx  = threadIdx.x;   // 0..31
    const int ty  = threadIdx.y;   // 0..7

    #pragma unroll
    for (int j = 0; j < 8; j++) {
        const int cl = ty + j * 8;
        tile[cl][tx] = x[((size_t)b * Cn + c0 + cl) * HWn + hw0 + tx];
    }
    __syncthreads();

    const int t = ty * 32 + tx;
    __half2* xt2 = reinterpret_cast<__half2*>(g_xt) + (c0 >= 64 ? PLANE_HALF2 : 0);
    #pragma unroll
    for (int j = 0; j < 4; j++) {
        const int idx  = j * 256 + t;          // 0..1023
        const int hw_l = idx >> 5;             // 0..31
        const int c2   = idx & 31;             // half2 index within 64-ch row
        const float f0 = tile[c2 * 2][hw_l];
        const float f1 = tile[c2 * 2 + 1][hw_l];
        xt2[((size_t)b * HWn + hw0 + hw_l) * 32 + c2] = __floats2half2_rn(f0, f1);
    }
}

// ---------------------------------------------------------------------------
// Kernel 2: gather + vote accumulate. ONE WARP PER POINT.
// Identical to round-11 except the gather loads bypass L1 allocation.
// ---------------------------------------------------------------------------
__global__ __launch_bounds__(256, 8) void gather_kernel(
    const int*   __restrict__ vote_index,   // [32768, 32]
    const float* __restrict__ vote_weight,  // [32768, 32]
    const int*   __restrict__ inds,         // [B, P] int32
    float*       __restrict__ out)          // [B, C, P]
{
    __shared__ uint2 s_iw[PT][Vn];   // {hw * 16 (uint2 row offset), half2(w,w)}
    __shared__ float s_out[PT][132];

    const int b    = blockIdx.y;
    const int p0   = blockIdx.x * PT;
    const int t    = threadIdx.x;
    const int warp = t >> 5;
    const int lane = t & 31;

    // Stage fused (row offset in uint2 units, weight half2) per vote.
    {
        const int sph = inds[(size_t)b * Pn + p0 + warp];   // warp-uniform
        const int hw  = vote_index[(size_t)sph * Vn + lane];
        const float w = vote_weight[(size_t)sph * Vn + lane];
        const __half2 w2 = __float2half2_rn(w);
        s_iw[warp][lane] = make_uint2((unsigned)hw * 16u,
                                      *reinterpret_cast<const unsigned*>(&w2));
    }
    __syncthreads();

    // Per-lane base: plane select + batch base + lane slot within 16-uint2 row.
    const uint2* xt = reinterpret_cast<const uint2*>(g_xt)
                    + (lane >= 16 ? PLANE_UINT2 : 0)
                    + (size_t)b * HWn * 16
                    + (lane & 15);

    float2 accA = make_float2(0.f, 0.f);
    float2 accB = make_float2(0.f, 0.f);

    #pragma unroll
    for (int g = 0; g < Vn / 4; g++) {           // 8 groups of 4 votes
        const uint2 iw0 = s_iw[warp][g * 4 + 0];
        const uint2 iw1 = s_iw[warp][g * 4 + 1];
        const uint2 iw2 = s_iw[warp][g * 4 + 2];
        const uint2 iw3 = s_iw[warp][g * 4 + 3];
        const uint2 r0 = ldg_na(xt + iw0.x);
        const uint2 r1 = ldg_na(xt + iw1.x);
        const uint2 r2 = ldg_na(xt + iw2.x);
        const uint2 r3 = ldg_na(xt + iw3.x);

        __half2 h0 = __float2half2_rn(0.f);
        __half2 h1 = __float2half2_rn(0.f);
        h0 = __hfma2(*reinterpret_cast<const __half2*>(&r0.x),
                     *reinterpret_cast<const __half2*>(&iw0.y), h0);
        h1 = __hfma2(*reinterpret_cast<const __half2*>(&r0.y),
                     *reinterpret_cast<const __half2*>(&iw0.y), h1);
        h0 = __hfma2(*reinterpret_cast<const __half2*>(&r1.x),
                     *reinterpret_cast<const __half2*>(&iw1.y), h0);
        h1 = __hfma2(*reinterpret_cast<const __half2*>(&r1.y),
                     *reinterpret_cast<const __half2*>(&iw1.y), h1);
        h0 = __hfma2(*reinterpret_cast<const __half2*>(&r2.x),
                     *reinterpret_cast<const __half2*>(&iw2.y), h0);
        h1 = __hfma2(*reinterpret_cast<const __half2*>(&r2.y),
                     *reinterpret_cast<const __half2*>(&iw2.y), h1);
        h0 = __hfma2(*reinterpret_cast<const __half2*>(&r3.x),
                     *reinterpret_cast<const __half2*>(&iw3.y), h0);
        h1 = __hfma2(*reinterpret_cast<const __half2*>(&r3.y),
                     *reinterpret_cast<const __half2*>(&iw3.y), h1);

        const float2 f0 = __half22float2(h0);
        const float2 f1 = __half22float2(h1);
        accA.x += f0.x; accA.y += f0.y;
        accB.x += f1.x; accB.y += f1.y;
    }

    // Lane l holds channels 4l..4l+3 (plane split preserves this mapping).
    *reinterpret_cast<float4*>(&s_out[warp][lane * 4]) =
        make_float4(accA.x, accA.y, accB.x, accB.y);
    __syncthreads();

    // Write out [C][PT] tile: 8 consecutive p per c row.
    #pragma unroll
    for (int i = t; i < Cn * PT; i += 256) {
        const int c  = i >> 3;   // i / PT
        const int pl = i & 7;    // i % PT
        out[((size_t)b * Cn + c) * Pn + p0 + pl] = s_out[pl][c];
    }
}

// ---------------------------------------------------------------------------
// Launch
// ---------------------------------------------------------------------------
extern "C" void kernel_launch(void* const* d_in, const int* in_sizes, int n_in,
                              void* d_out, int out_size)
{
    const float* x           = (const float*)d_in[0];   // [4,128,128,128]
    const int*   vote_index  = (const int*)d_in[1];     // [32768,32]
    const float* vote_weight = (const float*)d_in[2];   // [32768,32]
    const int*   inds        = (const int*)d_in[3];     // [4,4096] int32
    float*       out         = (float*)d_out;           // [4,128,4096]

    {
        dim3 grid(HWn / 32, Cn / 64, Bn);   // (512, 2, 4)
        dim3 block(32, 8);
        transpose_fp16_kernel<<<grid, block>>>(x);
    }
    {
        dim3 grid(Pn / PT, Bn);             // (512, 4) = 2048 blocks
        gather_kernel<<<grid, 256>>>(vote_index, vote_weight, inds, out);
    }
}

// round 14
// speedup vs baseline: 1.2688x; 1.0014x over previous
#include <cuda_runtime.h>
#include <cuda_fp16.h>
#include <cstdint>

// Problem constants (fixed by the reference)
#define Bn   4
#define Cn   128
#define HWn  16384      // 128*128
#define Pn   4096
#define Vn   32
#define PT   8          // points per block (1 warp per point)

// Split-plane fp16 scratch: plane A = channels 0..63, plane B = channels
// 64..127, each [B][HW][64] halves (128B rows).
#define PLANE_HALF2 ((size_t)Bn * HWn * 32)   // half2 units per plane
#define PLANE_UINT2 ((size_t)Bn * HWn * 16)   // uint2 units per plane
__device__ __align__(16) __half g_xt[(size_t)2 * Bn * HWn * 64];

// Gather load: read-only, no L1 allocation (best measured variant).
__device__ __forceinline__ uint2 ldg_na(const uint2* p)
{
    uint2 r;
    asm volatile("ld.global.nc.L1::no_allocate.v2.u32 {%0,%1}, [%2];"
                 : "=r"(r.x), "=r"(r.y) : "l"(p));
    return r;
}

// ---------------------------------------------------------------------------
// Kernel 1: transpose + downconvert x [B,C,HW] fp32 -> split planes.
// DRAM-roofline bound (~50MB @ ~7.4TB/s measured); leave alone.
// ---------------------------------------------------------------------------
__global__ __launch_bounds__(256) void transpose_fp16_kernel(const float* __restrict__ x)
{
    __shared__ float tile[64][33];

    const int b   = blockIdx.z;
    const int hw0 = blockIdx.x * 32;
    const int c0  = blockIdx.y * 64;     // 0 or 64 -> plane select
    const int tx  = threadIdx.x;   // 0..31
    const int ty  = threadIdx.y;   // 0..7

    #pragma unroll
    for (int j = 0; j < 8; j++) {
        const int cl = ty + j * 8;
        tile[cl][tx] = x[((size_t)b * Cn + c0 + cl) * HWn + hw0 + tx];
    }
    __syncthreads();

    const int t = ty * 32 + tx;
    __half2* xt2 = reinterpret_cast<__half2*>(g_xt) + (c0 >= 64 ? PLANE_HALF2 : 0);
    #pragma unroll
    for (int j = 0; j < 4; j++) {
        const int idx  = j * 256 + t;          // 0..1023
        const int hw_l = idx >> 5;             // 0..31
        const int c2   = idx & 31;             // half2 index within 64-ch row
        const float f0 = tile[c2 * 2][hw_l];
        const float f1 = tile[c2 * 2 + 1][hw_l];
        xt2[((size_t)b * HWn + hw0 + hw_l) * 32 + c2] = __floats2half2_rn(f0, f1);
    }
}

// ---------------------------------------------------------------------------
// Kernel 2: gather + vote accumulate. ONE WARP PER POINT.
// Software pipeline depth 2: group g+1's offsets are loaded and its 4 LDGs
// issued BEFORE consuming group g -> 8 gathers (2KB) in flight per warp and
// the LDS->LDG dependency is off the critical path. (256,7): ~36-reg budget,
// 7 blocks/SM = 56 warps (87% occ) -- the depth/occupancy cell r8/r9 missed.
// ---------------------------------------------------------------------------
__global__ __launch_bounds__(256, 7) void gather_kernel(
    const int*   __restrict__ vote_index,   // [32768, 32]
    const float* __restrict__ vote_weight,  // [32768, 32]
    const int*   __restrict__ inds,         // [B, P] int32
    float*       __restrict__ out)          // [B, C, P]
{
    __shared__ uint2 s_iw[PT][Vn];   // {hw * 16 (uint2 row offset), half2(w,w)}
    __shared__ float s_out[PT][132];

    const int b    = blockIdx.y;
    const int p0   = blockIdx.x * PT;
    const int t    = threadIdx.x;
    const int warp = t >> 5;
    const int lane = t & 31;

    // Stage fused (row offset in uint2 units, weight half2) per vote.
    {
        const int sph = inds[(size_t)b * Pn + p0 + warp];   // warp-uniform
        const int hw  = vote_index[(size_t)sph * Vn + lane];
        const float w = vote_weight[(size_t)sph * Vn + lane];
        const __half2 w2 = __float2half2_rn(w);
        s_iw[warp][lane] = make_uint2((unsigned)hw * 16u,
                                      *reinterpret_cast<const unsigned*>(&w2));
    }
    __syncthreads();

    // Per-lane base: plane select + batch base + lane slot within 16-uint2 row.
    const uint2* xt = reinterpret_cast<const uint2*>(g_xt)
                    + (lane >= 16 ? PLANE_UINT2 : 0)
                    + (size_t)b * HWn * 16
                    + (lane & 15);

    float2 accA = make_float2(0.f, 0.f);
    float2 accB = make_float2(0.f, 0.f);

    // Pipeline prologue: group 0 offsets + gathers in flight.
    uint2 iw[2][4], r[2][4];
    #pragma unroll
    for (int k = 0; k < 4; k++) {
        iw[0][k] = s_iw[warp][k];
        r[0][k]  = ldg_na(xt + iw[0][k].x);
    }

    #pragma unroll
    for (int g = 0; g < Vn / 4; g++) {           // 8 groups of 4 votes
        const int cur = g & 1;
        const int nxt = cur ^ 1;
        // Issue group g+1's gathers before consuming group g.
        if (g < Vn / 4 - 1) {
            #pragma unroll
            for (int k = 0; k < 4; k++) {
                iw[nxt][k] = s_iw[warp][(g + 1) * 4 + k];
                r[nxt][k]  = ldg_na(xt + iw[nxt][k].x);
            }
        }

        __half2 h0 = __float2half2_rn(0.f);
        __half2 h1 = __float2half2_rn(0.f);
        #pragma unroll
        for (int k = 0; k < 4; k++) {
            const __half2 w2 = *reinterpret_cast<const __half2*>(&iw[cur][k].y);
            h0 = __hfma2(*reinterpret_cast<const __half2*>(&r[cur][k].x), w2, h0);
            h1 = __hfma2(*reinterpret_cast<const __half2*>(&r[cur][k].y), w2, h1);
        }
        const float2 f0 = __half22float2(h0);
        const float2 f1 = __half22float2(h1);
        accA.x += f0.x; accA.y += f0.y;
        accB.x += f1.x; accB.y += f1.y;
    }

    // Lane l holds channels 4l..4l+3 (plane split preserves this mapping).
    *reinterpret_cast<float4*>(&s_out[warp][lane * 4]) =
        make_float4(accA.x, accA.y, accB.x, accB.y);
    __syncthreads();

    // Write out [C][PT] tile: 8 consecutive p per c row.
    #pragma unroll
    for (int i = t; i < Cn * PT; i += 256) {
        const int c  = i >> 3;   // i / PT
        const int pl = i & 7;    // i % PT
        out[((size_t)b * Cn + c) * Pn + p0 + pl] = s_out[pl][c];
    }
}

// ---------------------------------------------------------------------------
// Launch (two default-stream launches: capture-safe, allocation-free)
// ---------------------------------------------------------------------------
extern "C" void kernel_launch(void* const* d_in, const int* in_sizes, int n_in,
                              void* d_out, int out_size)
{
    const float* x           = (const float*)d_in[0];   // [4,128,128,128]
    const int*   vote_index  = (const int*)d_in[1];     // [32768,32]
    const float* vote_weight = (const float*)d_in[2];   // [32768,32]
    const int*   inds        = (const int*)d_in[3];     // [4,4096] int32
    float*       out         = (float*)d_out;           // [4,128,4096]

    {
        dim3 grid(HWn / 32, Cn / 64, Bn);   // (512, 2, 4)
        dim3 block(32, 8);
        transpose_fp16_kernel<<<grid, block>>>(x);
    }
    {
        dim3 grid(Pn / PT, Bn);             // (512, 4) = 2048 blocks
        gather_kernel<<<grid, 256>>>(vote_index, vote_weight, inds, out);
    }
}